// round 14
// baseline (speedup 1.0000x reference)
#include <cuda_runtime.h>

#define K 7
#define HH 1024
#define WW 1024
#define NBINS (K * K)
#define CHUNKS 16
#define NPROD (NBINS * CHUNKS)       // 784 producer blocks
#define TPB 128
#define NWARPS (TPB / 32)

// Single packed accumulator: bits[54:64) = arrival count, bits[0:54) = biased
// fixed-point sum (scale 2^44, per-publish bias 2^43). Zero-init; last block
// resets it each run. Integer adds => exactly deterministic.
__device__ unsigned long long g_acc;

#define COUNT_SHIFT 54
#define BIAS        (1ll << 43)
#define SCALE       0x1p44f
#define INV_SCALE   0x1p-44
#define VALUE_MASK  ((1ull << COUNT_SHIFT) - 1ull)

__device__ __forceinline__ void bin_extents(float ci, float cj, float h, float w,
                                            int bi, int bj,
                                            int& r0, int& r1, int& c0, int& c1) {
    // Mirror the reference float32 arithmetic.
    float i0 = ci - h * 0.5f, i1 = ci + h * 0.5f;
    float j0 = cj - w * 0.5f, j1 = cj + w * 0.5f;
    float stepi = (i1 - i0) / (float)(K + 1);
    float stepj = (j1 - j0) / (float)(K + 1);
    float ic = i0 + (float)(bi + 1) * stepi;
    float jc = j0 + (float)(bj + 1) * stepj;
    float bh2 = h / (float)K * 0.5f;
    float bw2 = w / (float)K * 0.5f;
    r0 = (int)floorf((ic - bh2) * (float)HH);
    r1 = (int)ceilf ((ic + bh2) * (float)HH);
    c0 = (int)floorf((jc - bw2) * (float)WW);
    c1 = (int)ceilf ((jc + bw2) * (float)WW);
    r0 = max(r0, 0); r1 = min(r1, HH);
    c0 = max(c0, 0); c1 = min(c1, WW);
}

__global__ __launch_bounds__(TPB)
void psroi_pc_kernel(const float* __restrict__ x,
                     const float* __restrict__ region,
                     float* __restrict__ out) {
    const int blk   = blockIdx.x;         // 0..NPROD-1
    const int bin   = blk >> 4;           // /CHUNKS
    const int chunk = blk & (CHUNKS - 1);
    const int bi = bin / K, bj = bin % K;
    const int t    = threadIdx.x;
    const int wid  = t >> 5;
    const int lane = t & 31;

    const float4 reg = *reinterpret_cast<const float4*>(region);

    int r0, r1, c0, c1;
    bin_extents(reg.x, reg.y, reg.z, reg.w, bi, bj, r0, r1, c0, c1);

    const int total = (r1 - r0) * (c1 - c0);    // full-bin count (for scale)
    const int rpc   = (r1 - r0 + CHUNKS - 1) / CHUNKS;
    const int cr0   = r0 + chunk * rpc;
    const int cr1   = min(r1, cr0 + rpc);

    const float* __restrict__ chan = x + (size_t)bin * HH * WW;

    // warp-per-row, lane-per-column: coalesced, division-free, short chains
    float acc = 0.0f;
    for (int r = cr0 + wid; r < cr1; r += NWARPS) {
        const float* __restrict__ rowp = chan + (size_t)r * WW;
        for (int c = c0 + lane; c < c1; c += 32)
            acc += __ldg(rowp + c);
    }

    // block reduce: warp shuffle, then thread 0 over 4 leaders
    #pragma unroll
    for (int o = 16; o > 0; o >>= 1)
        acc += __shfl_down_sync(0xffffffffu, acc, o);

    __shared__ float s[NWARPS];
    if (lane == 0) s[wid] = acc;
    __syncthreads();

    if (t == 0) {
        float v = s[0];
        #pragma unroll
        for (int i = 1; i < NWARPS; i++) v += s[i];
        v /= ((float)total * (float)NBINS);       // |v| < 1e-2

        // pack: count-unit + biased fixed-point value; ONE atomic with return.
        long long q = __float2ll_rn(v * SCALE);
        unsigned long long w = (1ull << COUNT_SHIFT)
                             + (unsigned long long)(q + BIAS);
        unsigned long long prev = atomicAdd(&g_acc, w);
        unsigned long long now  = prev + w;

        if ((now >> COUNT_SHIFT) == (unsigned long long)NPROD) {
            // this block is last: 'now' holds the complete, exact sum.
            long long qs = (long long)(now & VALUE_MASK)
                         - (long long)NPROD * BIAS;
            out[0] = (float)((double)qs * INV_SCALE);
            g_acc = 0ull;            // reset for next graph replay
        }
    }
}

extern "C" void kernel_launch(void* const* d_in, const int* in_sizes, int n_in,
                              void* d_out, int out_size) {
    const float* x      = (const float*)d_in[0];
    const float* region = (const float*)d_in[1];
    float* out = (float*)d_out;

    psroi_pc_kernel<<<NPROD, TPB>>>(x, region, out);
}